// round 1
// baseline (speedup 1.0000x reference)
#include <cuda_runtime.h>
#include <cstdint>

// S4D kernel materialization:
//   K[h, l] = 2 * Re( sum_n  S0[h,n] * exp(dtA[h,n])^l ),
//   S0 = C * (exp(dtA) - 1) / A  (discretization folded into the state).
//
// Strategy: block per h (1024 blocks, 128 threads). Thread t owns the L-slice
// l = t, t+128, t+256, ... (coalesced stores). State S[n] advances by the
// precomputed per-(h,n) factor step = exp(dtA)^128 each iteration (complex
// multiply). Two n's are packed per 64-bit register and updated with
// fma/mul/add.rn.f32x2 (Blackwell packed fp32) -> 5 packed instrs per n-pair
// per l instead of 10 scalar FMAs.

#define HH      1024
#define NHALF   32
#define LLEN    8192
#define TPB     128
#define NSTEP   (LLEN / TPB)   // 64 l-values per thread
#define PAIRS   (NHALF / 2)    // 16 packed complex states

__device__ __forceinline__ unsigned long long pk2(float lo, float hi) {
    unsigned long long r;
    asm("mov.b64 %0, {%1, %2};" : "=l"(r) : "f"(lo), "f"(hi));
    return r;
}
__device__ __forceinline__ void upk2(unsigned long long v, float& lo, float& hi) {
    asm("mov.b64 {%0, %1}, %2;" : "=f"(lo), "=f"(hi) : "l"(v));
}
__device__ __forceinline__ unsigned long long ffma2(unsigned long long a,
                                                    unsigned long long b,
                                                    unsigned long long c) {
    unsigned long long d;
    asm("fma.rn.f32x2 %0, %1, %2, %3;" : "=l"(d) : "l"(a), "l"(b), "l"(c));
    return d;
}
__device__ __forceinline__ unsigned long long fmul2(unsigned long long a,
                                                    unsigned long long b) {
    unsigned long long d;
    asm("mul.rn.f32x2 %0, %1, %2;" : "=l"(d) : "l"(a), "l"(b));
    return d;
}
__device__ __forceinline__ unsigned long long fadd2(unsigned long long a,
                                                    unsigned long long b) {
    unsigned long long d;
    asm("add.rn.f32x2 %0, %1, %2;" : "=l"(d) : "l"(a), "l"(b));
    return d;
}

__global__ __launch_bounds__(TPB)
void s4d_kernel(const float* __restrict__ C,
                const float* __restrict__ log_dt,
                const float* __restrict__ log_A_real,
                const float* __restrict__ A_imag,
                float* __restrict__ out)
{
    __shared__ float sh_s0r[NHALF], sh_s0i[NHALF];   // S0 = C*(exp(dtA)-1)/A
    __shared__ float sh_str[NHALF], sh_sti[NHALF];   // step = exp(dtA)^TPB
    __shared__ float sh_dar[NHALF], sh_dai[NHALF];   // dtA (fp32, matches ref rounding)

    const int h = blockIdx.x;
    const int t = threadIdx.x;

    const double TWO_PI  = 6.283185307179586476925286766559;
    const double INV_2PI = 0.15915494309189533576888376337251;

    // ---- per-(h,n) setup in fp64 (32 threads) ----
    if (t < NHALF) {
        const int n = t;
        double dt = exp((double)log_dt[h]);
        double Ar = -exp((double)log_A_real[h * NHALF + n]);
        double Ai = (double)A_imag[h * NHALF + n];
        float darf = (float)(Ar * dt);   // dtA.re, rounded like the reference
        float daif = (float)(Ai * dt);   // dtA.im
        sh_dar[n] = darf;
        sh_dai[n] = daif;
        double dar = (double)darf, dai = (double)daif;

        // step = exp(dtA * TPB), phase reduced mod 2*pi in double
        double ph  = dai * (double)TPB;
        double kk  = rint(ph * INV_2PI);
        double phr = fma(-kk, TWO_PI, ph);
        double mg  = exp(dar * (double)TPB);
        sh_str[n] = (float)(mg * cos(phr));
        sh_sti[n] = (float)(mg * sin(phr));

        // S0 = C * (exp(dtA) - 1) / A
        double e1 = exp(dar);
        double er = e1 * cos(dai), ei = e1 * sin(dai);
        double nr = er - 1.0, ni = ei;
        double den = Ar * Ar + Ai * Ai;
        double qr = (nr * Ar + ni * Ai) / den;
        double qi = (ni * Ar - nr * Ai) / den;
        double Cr = (double)C[(h * NHALF + n) * 2 + 0];
        double Ci = (double)C[(h * NHALF + n) * 2 + 1];
        sh_s0r[n] = (float)(Cr * qr - Ci * qi);
        sh_s0i[n] = (float)(Cr * qi + Ci * qr);
    }
    __syncthreads();

    // ---- per-thread init: S[n] = S0[n] * exp(dtA * t) ----
    unsigned long long Sr[PAIRS], Si[PAIRS];          // packed states (2 n's per reg)
    unsigned long long Er[PAIRS], Ei[PAIRS], En[PAIRS]; // step.re, step.im, -step.im

    const float tf = (float)t;

#pragma unroll
    for (int p = 0; p < PAIRS; ++p) {
        float vr[2], vi[2];
#pragma unroll
        for (int q = 0; q < 2; ++q) {
            int n = 2 * p + q;
            float dai = sh_dai[n];
            double th = (double)dai * (double)t;      // exact in double
            double kk = rint(th * INV_2PI);
            float thr = (float)fma(-kk, TWO_PI, th);  // |thr| <= pi
            float s, c;
            __sincosf(thr, &s, &c);
            float m  = __expf(sh_dar[n] * tf);
            float br = m * c, bi = m * s;
            float s0r = sh_s0r[n], s0i = sh_s0i[n];
            vr[q] = s0r * br - s0i * bi;
            vi[q] = s0r * bi + s0i * br;
        }
        Sr[p] = pk2(vr[0], vr[1]);
        Si[p] = pk2(vi[0], vi[1]);
        Er[p] = pk2(sh_str[2 * p], sh_str[2 * p + 1]);
        Ei[p] = pk2(sh_sti[2 * p], sh_sti[2 * p + 1]);
        En[p] = pk2(-sh_sti[2 * p], -sh_sti[2 * p + 1]);
    }

    // ---- main loop: 64 l-steps, 16 independent packed complex chains ----
    float* outp = out + (size_t)h * LLEN + t;

#pragma unroll 1
    for (int j = 0; j < NSTEP; ++j) {
        unsigned long long acc = 0ull;                // (0.0f, 0.0f)
#pragma unroll
        for (int p = 0; p < PAIRS; ++p) {
            acc = fadd2(acc, Sr[p]);                              // K += Re(S)
            unsigned long long t1 = fmul2(Si[p], En[p]);          // -Si*ei
            unsigned long long t2 = fmul2(Sr[p], Ei[p]);          //  Sr*ei
            Sr[p] = ffma2(Sr[p], Er[p], t1);                      // Sr*er - Si*ei
            Si[p] = ffma2(Si[p], Er[p], t2);                      // Si*er + Sr*ei
        }
        float lo, hi;
        upk2(acc, lo, hi);
        outp[(size_t)j * TPB] = 2.0f * (lo + hi);
    }
}

extern "C" void kernel_launch(void* const* d_in, const int* in_sizes, int n_in,
                              void* d_out, int out_size) {
    (void)in_sizes; (void)n_in; (void)out_size;
    const float* C          = (const float*)d_in[0];
    const float* log_dt     = (const float*)d_in[1];
    const float* log_A_real = (const float*)d_in[2];
    const float* A_imag     = (const float*)d_in[3];
    float* out = (float*)d_out;
    s4d_kernel<<<HH, TPB>>>(C, log_dt, log_A_real, A_imag, out);
}

// round 2
// speedup vs baseline: 1.1618x; 1.1618x over previous
#include <cuda_runtime.h>
#include <cstdint>

// S4D kernel materialization via per-mode real 2-term recurrence.
//   K[h,l] = 2*Re( sum_n S0[h,n] * exp(dtA[h,n])^l ),  S0 = C*(exp(dtA)-1)/A
// Thread t of block h owns l = t + 128*j (j=0..63, coalesced stores).
// Per n, x_j = Re(S_t * z^j) with z = exp(dtA*128) obeys
//   x_{j+1} = a*x_j + b*x_{j-1},  a = 2*Re(z), b = -|z|^2   (|z| <= 0.53: stable)
// Two n's packed per 64-bit reg -> 3 packed fma-pipe instrs per pair per output.

#define HH      1024
#define NHALF   32
#define LLEN    8192
#define TPB     128
#define NSTEP   (LLEN / TPB)   // 64 outputs per thread
#define PAIRS   (NHALF / 2)    // 16 packed chains

typedef unsigned long long u64;

__device__ __forceinline__ u64 pk2(float lo, float hi) {
    u64 r; asm("mov.b64 %0, {%1, %2};" : "=l"(r) : "f"(lo), "f"(hi)); return r;
}
__device__ __forceinline__ void upk2(u64 v, float& lo, float& hi) {
    asm("mov.b64 {%0, %1}, %2;" : "=f"(lo), "=f"(hi) : "l"(v));
}
__device__ __forceinline__ u64 ffma2(u64 a, u64 b, u64 c) {
    u64 d; asm("fma.rn.f32x2 %0, %1, %2, %3;" : "=l"(d) : "l"(a), "l"(b), "l"(c)); return d;
}
__device__ __forceinline__ u64 fmul2(u64 a, u64 b) {
    u64 d; asm("mul.rn.f32x2 %0, %1, %2;" : "=l"(d) : "l"(a), "l"(b)); return d;
}
__device__ __forceinline__ u64 fadd2(u64 a, u64 b) {
    u64 d; asm("add.rn.f32x2 %0, %1, %2;" : "=l"(d) : "l"(a), "l"(b)); return d;
}

__global__ __launch_bounds__(TPB, 3)
void s4d_kernel(const float* __restrict__ C,
                const float* __restrict__ log_dt,
                const float* __restrict__ log_A_real,
                const float* __restrict__ A_imag,
                float* __restrict__ out)
{
    __shared__ float sh_s0r[NHALF], sh_s0i[NHALF];   // 2 * C*(exp(dtA)-1)/A
    __shared__ float sh_dar[NHALF], sh_dai[NHALF];   // dtA (fp32-rounded like ref)
    __shared__ float sh_a[NHALF],  sh_b[NHALF];      // a = 2*Re(z), b = -|z|^2
    __shared__ float sh_ir[NHALF], sh_ii[NHALF];     // z^{-1} = conj(z)/|z|^2

    const int h = blockIdx.x;
    const int t = threadIdx.x;

    const double TWO_PI  = 6.283185307179586476925286766559;
    const double INV_2PI = 0.15915494309189533576888376337251;

    // ---- per-(h,n) setup in fp64 (32 threads) ----
    if (t < NHALF) {
        const int n = t;
        double dt = exp((double)log_dt[h]);
        double Ar = -exp((double)log_A_real[h * NHALF + n]);
        double Ai = (double)A_imag[h * NHALF + n];
        float darf = (float)(Ar * dt);
        float daif = (float)(Ai * dt);
        sh_dar[n] = darf;
        sh_dai[n] = daif;
        double dar = (double)darf, dai = (double)daif;

        // z = exp(dtA * 128), phase reduced in double
        double ph  = dai * (double)TPB;
        double kk  = rint(ph * INV_2PI);
        double phr = fma(-kk, TWO_PI, ph);
        double mg  = exp(dar * (double)TPB);
        double er  = mg * cos(phr), ei = mg * sin(phr);
        sh_a[n]  = (float)(2.0 * er);
        sh_b[n]  = (float)(-(mg * mg));
        sh_ir[n] = (float)(cos(phr) / mg);       // Re(z^-1)
        sh_ii[n] = (float)(-sin(phr) / mg);      // Im(z^-1)

        // S0 = 2 * C * (exp(dtA) - 1) / A   (fold the final 2x here)
        double e1 = exp(dar);
        double cr = e1 * cos(dai) - 1.0, ci = e1 * sin(dai);
        double den = Ar * Ar + Ai * Ai;
        double qr = (cr * Ar + ci * Ai) / den;
        double qi = (ci * Ar - cr * Ai) / den;
        double Cr = (double)C[(h * NHALF + n) * 2 + 0];
        double Ci = (double)C[(h * NHALF + n) * 2 + 1];
        sh_s0r[n] = (float)(2.0 * (Cr * qr - Ci * qi));
        sh_s0i[n] = (float)(2.0 * (Cr * qi + Ci * qr));
    }
    __syncthreads();

    // ---- per-thread seed: x_{-1}, x_0 for each n; S_t = S0 * exp(dtA*t) ----
    u64 Xm[PAIRS], Xc[PAIRS];   // x_{j-1}, x_j   (packed pairs of n)
    u64 Aa[PAIRS], Bb[PAIRS];   // recurrence coefficients

    const float tf = (float)t;

#pragma unroll
    for (int p = 0; p < PAIRS; ++p) {
        float x0[2], xm1[2];
#pragma unroll
        for (int q = 0; q < 2; ++q) {
            int n = 2 * p + q;
            double th = (double)sh_dai[n] * (double)t;   // exact phase in double
            double kk = rint(th * INV_2PI);
            float thr = (float)fma(-kk, TWO_PI, th);     // |thr| <= pi
            float s, c;
            __sincosf(thr, &s, &c);
            float m  = __expf(sh_dar[n] * tf);
            float br = m * c, bi = m * s;                // exp(dtA * t)
            float Str = sh_s0r[n] * br - sh_s0i[n] * bi; // S_t
            float Sti = sh_s0r[n] * bi + sh_s0i[n] * br;
            x0[q]  = Str;                                // Re(S_t)
            xm1[q] = Str * sh_ir[n] - Sti * sh_ii[n];    // Re(S_t * z^-1)
        }
        Xc[p] = pk2(x0[0],  x0[1]);
        Xm[p] = pk2(xm1[0], xm1[1]);
        Aa[p] = pk2(sh_a[2 * p], sh_a[2 * p + 1]);
        Bb[p] = pk2(sh_b[2 * p], sh_b[2 * p + 1]);
    }

    // ---- main loop: 64 outputs, unrolled by 2 with ping-pong (no MOVs) ----
    float* outp = out + (size_t)h * LLEN + t;

#pragma unroll 1
    for (int j = 0; j < NSTEP; j += 2) {
        u64 acc = 0ull;
#pragma unroll
        for (int p = 0; p < PAIRS; ++p) {
            acc   = fadd2(acc, Xc[p]);                       // output j
            Xm[p] = ffma2(Xc[p], Aa[p], fmul2(Xm[p], Bb[p])); // x_{j+1}
        }
        float lo, hi;
        upk2(acc, lo, hi);
        outp[(size_t)j * TPB] = lo + hi;

        acc = 0ull;
#pragma unroll
        for (int p = 0; p < PAIRS; ++p) {
            acc   = fadd2(acc, Xm[p]);                       // output j+1
            Xc[p] = ffma2(Xm[p], Aa[p], fmul2(Xc[p], Bb[p])); // x_{j+2}
        }
        upk2(acc, lo, hi);
        outp[(size_t)(j + 1) * TPB] = lo + hi;
    }
}

extern "C" void kernel_launch(void* const* d_in, const int* in_sizes, int n_in,
                              void* d_out, int out_size) {
    (void)in_sizes; (void)n_in; (void)out_size;
    const float* C          = (const float*)d_in[0];
    const float* log_dt     = (const float*)d_in[1];
    const float* log_A_real = (const float*)d_in[2];
    const float* A_imag     = (const float*)d_in[3];
    float* out = (float*)d_out;
    s4d_kernel<<<HH, TPB>>>(C, log_dt, log_A_real, A_imag, out);
}